// round 1
// baseline (speedup 1.0000x reference)
#include <cuda_runtime.h>

// Problem constants (fixed shapes from reference setup_inputs)
#define B_DIM 128
#define N_DIM 1024
#define K_DIM 512            // D*S = 8*64
#define K_VEC (K_DIM / 4)    // 128 float4 per row
#define ALPHA 0.05f
#define THETA_LR 0.1f
#define R_TARGET 0.1f

// Kernel 1: one warp per (b, n). Computes v = dot(x[b,n,:], W[n,:]) and the
// hard-threshold spike. Warp id maps b-major / n-minor so consecutive warps
// stream contiguous x and contiguous W (W: 2 MB, fully L2-resident).
__global__ __launch_bounds__(256) void mpjrd_dot_spike(
    const float4* __restrict__ x,     // [B*N, 128] float4
    const float4* __restrict__ W,     // [N, 128] float4
    const float* __restrict__ theta,  // [N]
    float* __restrict__ spikes)       // [B*N]
{
    const int warp = (blockIdx.x * blockDim.x + threadIdx.x) >> 5;
    const int lane = threadIdx.x & 31;
    // warp in [0, B*N)
    const int n = warp & (N_DIM - 1);

    const float4* xr = x + (size_t)warp * K_VEC;
    const float4* wr = W + (size_t)n * K_VEC;

    float acc = 0.0f;
#pragma unroll
    for (int k = 0; k < 4; k++) {
        const float4 a = xr[lane + 32 * k];
        const float4 w = wr[lane + 32 * k];
        acc = fmaf(a.x, w.x, acc);
        acc = fmaf(a.y, w.y, acc);
        acc = fmaf(a.z, w.z, acc);
        acc = fmaf(a.w, w.w, acc);
    }
    // warp tree reduction
#pragma unroll
    for (int off = 16; off > 0; off >>= 1)
        acc += __shfl_xor_sync(0xFFFFFFFFu, acc, off);

    if (lane == 0) {
        spikes[warp] = (acc >= __ldg(&theta[n])) ? 1.0f : 0.0f;
    }
}

// Kernel 2: per-neuron reduction of spikes over batch + homeostatic updates.
// One block of 128 threads per neuron n; thread t reads spikes[t*N + n].
__global__ __launch_bounds__(128) void mpjrd_rate_update(
    const float* __restrict__ spikes, // [B, N]
    const float* __restrict__ theta,  // [N]
    const float* __restrict__ r_hat,  // [N]
    float* __restrict__ rates,        // [N]
    float* __restrict__ thetas,       // [N]
    float* __restrict__ r_hats)       // [N]
{
    const int n = blockIdx.x;
    const int t = threadIdx.x;       // batch index
    const int lane = t & 31;
    const int wid = t >> 5;

    float s = spikes[(size_t)t * N_DIM + n];
#pragma unroll
    for (int off = 16; off > 0; off >>= 1)
        s += __shfl_xor_sync(0xFFFFFFFFu, s, off);

    __shared__ float partial[4];
    if (lane == 0) partial[wid] = s;
    __syncthreads();

    if (t == 0) {
        const float total = partial[0] + partial[1] + partial[2] + partial[3];
        const float rate = total * (1.0f / (float)B_DIM);
        const float rh = (1.0f - ALPHA) * r_hat[n] + ALPHA * rate;
        const float th = theta[n] + THETA_LR * (rh - R_TARGET);
        rates[n] = rate;
        r_hats[n] = rh;
        thetas[n] = th;
    }
}

extern "C" void kernel_launch(void* const* d_in, const int* in_sizes, int n_in,
                              void* d_out, int out_size) {
    const float4* x     = (const float4*)d_in[0];   // [B, N, D, S] f32
    const float4* W     = (const float4*)d_in[1];   // [N, D, S] f32
    const float* theta  = (const float*)d_in[2];    // [N]
    const float* r_hat  = (const float*)d_in[3];    // [N]

    float* out    = (float*)d_out;
    float* spikes = out;                       // [B*N] = 131072
    float* rates  = out + B_DIM * N_DIM;       // [N]
    float* thetas = rates + N_DIM;             // [N]
    float* r_hats = thetas + N_DIM;            // [N]

    // 131072 warps total; 8 warps (256 threads) per block -> 16384 blocks
    mpjrd_dot_spike<<<(B_DIM * N_DIM) / 8, 256>>>(x, W, theta, spikes);
    mpjrd_rate_update<<<N_DIM, 128>>>(spikes, theta, r_hat, rates, thetas, r_hats);
}

// round 3
// speedup vs baseline: 1.0397x; 1.0397x over previous
#include <cuda_runtime.h>

// Shapes fixed by reference setup_inputs
#define B_DIM 128
#define N_DIM 1024
#define K_DIM 512            // D*S
#define K_VEC (K_DIM / 4)    // 128 float4 per row
#define ALPHA 0.05f
#define THETA_LR 0.1f
#define R_TARGET 0.1f

// Fully fused kernel.
// Grid: N/2 = 512 CTAs. Block: 256 threads = 8 warps.
// CTA c owns neurons n0 = 2c and n0+1 for ALL 128 batch rows:
//   warps 0-3 -> neuron n0, warps 4-7 -> neuron n0+1; warp (sub = w&3)
//   handles b in [sub*32, sub*32+32).
// Each warp loads its W row ONCE into 16 registers/lane (4 float4), then
// streams x rows with __ldcs (evict-first: x has zero reuse, keeps L2 clean).
// Since the CTA covers the full batch for its neurons, spike counts are
// combined in smem and rates/thetas/r_hats are computed here too — no
// second kernel, no atomics.
__global__ __launch_bounds__(256) void mpjrd_fused(
    const float4* __restrict__ x,     // [B, N, 128] float4
    const float4* __restrict__ W,     // [N, 128] float4
    const float* __restrict__ theta,  // [N]
    const float* __restrict__ r_hat,  // [N]
    float* __restrict__ spikes,       // [B, N]
    float* __restrict__ rates,        // [N]
    float* __restrict__ thetas,       // [N]
    float* __restrict__ r_hats)       // [N]
{
    const int tid  = threadIdx.x;
    const int w    = tid >> 5;        // warp 0..7
    const int lane = tid & 31;
    const int n0   = blockIdx.x * 2;
    const int n    = n0 + (w >> 2);   // this warp's neuron
    const int bb   = (w & 3) * 32;    // first batch row for this warp

    // W row into registers: lane covers float4 indices lane, lane+32, +64, +96
    const float4* wr = W + (size_t)n * K_VEC;
    float4 wreg[4];
#pragma unroll
    for (int k = 0; k < 4; k++) wreg[k] = __ldg(&wr[lane + 32 * k]);

    const float th = __ldg(&theta[n]);

    __shared__ int s_cnt[8];
    int cnt = 0;

    // 32 batch rows per warp, processed 2 at a time for MLP (8 LDG.128 in flight)
#pragma unroll 1
    for (int i = 0; i < 32; i += 2) {
        const int b0 = bb + i;
        const int b1 = bb + i + 1;
        const float4* x0 = x + ((size_t)b0 * N_DIM + n) * K_VEC;
        const float4* x1 = x + ((size_t)b1 * N_DIM + n) * K_VEC;

        float4 a0[4], a1[4];
#pragma unroll
        for (int k = 0; k < 4; k++) a0[k] = __ldcs(&x0[lane + 32 * k]);
#pragma unroll
        for (int k = 0; k < 4; k++) a1[k] = __ldcs(&x1[lane + 32 * k]);

        float acc0 = 0.0f, acc1 = 0.0f;
#pragma unroll
        for (int k = 0; k < 4; k++) {
            acc0 = fmaf(a0[k].x, wreg[k].x, acc0);
            acc0 = fmaf(a0[k].y, wreg[k].y, acc0);
            acc0 = fmaf(a0[k].z, wreg[k].z, acc0);
            acc0 = fmaf(a0[k].w, wreg[k].w, acc0);
            acc1 = fmaf(a1[k].x, wreg[k].x, acc1);
            acc1 = fmaf(a1[k].y, wreg[k].y, acc1);
            acc1 = fmaf(a1[k].z, wreg[k].z, acc1);
            acc1 = fmaf(a1[k].w, wreg[k].w, acc1);
        }

        // Butterfly reductions (interleaved to hide SHFL latency)
#pragma unroll
        for (int off = 16; off > 0; off >>= 1) {
            acc0 += __shfl_xor_sync(0xFFFFFFFFu, acc0, off);
            acc1 += __shfl_xor_sync(0xFFFFFFFFu, acc1, off);
        }

        if (lane == 0) {
            const float s0 = (acc0 >= th) ? 1.0f : 0.0f;
            const float s1 = (acc1 >= th) ? 1.0f : 0.0f;
            spikes[(size_t)b0 * N_DIM + n] = s0;
            spikes[(size_t)b1 * N_DIM + n] = s1;
            cnt += (int)s0 + (int)s1;
        }
    }

    if (lane == 0) s_cnt[w] = cnt;
    __syncthreads();

    // Threads 0,1 finalize neurons n0, n0+1
    if (tid < 2) {
        const int nn = n0 + tid;
        const int total = s_cnt[tid * 4 + 0] + s_cnt[tid * 4 + 1] +
                          s_cnt[tid * 4 + 2] + s_cnt[tid * 4 + 3];
        const float rate = (float)total * (1.0f / (float)B_DIM);
        const float rh = (1.0f - ALPHA) * r_hat[nn] + ALPHA * rate;
        const float thn = theta[nn] + THETA_LR * (rh - R_TARGET);
        rates[nn]  = rate;
        r_hats[nn] = rh;
        thetas[nn] = thn;
    }
}

extern "C" void kernel_launch(void* const* d_in, const int* in_sizes, int n_in,
                              void* d_out, int out_size) {
    const float4* x     = (const float4*)d_in[0];   // [B, N, D, S] f32
    const float4* W     = (const float4*)d_in[1];   // [N, D, S] f32
    const float* theta  = (const float*)d_in[2];    // [N]
    const float* r_hat  = (const float*)d_in[3];    // [N]

    float* out    = (float*)d_out;
    float* spikes = out;                       // [B*N]
    float* rates  = out + B_DIM * N_DIM;       // [N]
    float* thetas = rates + N_DIM;             // [N]
    float* r_hats = thetas + N_DIM;            // [N]

    mpjrd_fused<<<N_DIM / 2, 256>>>(x, W, theta, r_hat,
                                    spikes, rates, thetas, r_hats);
}

// round 4
// speedup vs baseline: 1.0716x; 1.0307x over previous
#include <cuda_runtime.h>

// Shapes fixed by reference setup_inputs
#define B_DIM 128
#define N_DIM 1024
#define K_DIM 512            // D*S
#define K_VEC (K_DIM / 4)    // 128 float4 per row
#define ALPHA 0.05f
#define THETA_LR 0.1f
#define R_TARGET 0.1f

// Fully fused kernel, one neuron per CTA.
// Grid: N = 1024 CTAs. Block: 128 threads = 4 warps.
// CTA n owns neuron n for ALL 128 batch rows; warp w handles b in
// [w*32, w*32+32). 1024 small CTAs fit in ONE wave (≈7 CTAs/SM, reg-limited
// cap ~11), so per-SM load imbalance drops from 4-vs-3 (15.6%) to 7-vs-6
// with mean 6.92 (1.2%) — this was the gap between 77.8% and ~90% DRAM.
// Each warp loads its W row ONCE into 16 registers/lane, then streams x
// rows with __ldcs (zero-reuse stream, evict-first). The CTA sees the full
// batch, so rates/thetas/r_hats finalize in-kernel — no second launch.
__global__ __launch_bounds__(128) void mpjrd_fused(
    const float4* __restrict__ x,     // [B, N, 128] float4
    const float4* __restrict__ W,     // [N, 128] float4
    const float* __restrict__ theta,  // [N]
    const float* __restrict__ r_hat,  // [N]
    float* __restrict__ spikes,       // [B, N]
    float* __restrict__ rates,        // [N]
    float* __restrict__ thetas,       // [N]
    float* __restrict__ r_hats)       // [N]
{
    const int tid  = threadIdx.x;
    const int w    = tid >> 5;        // warp 0..3
    const int lane = tid & 31;
    const int n    = blockIdx.x;      // this CTA's neuron
    const int bb   = w * 32;          // first batch row for this warp

    // W row into registers: lane covers float4 indices lane, lane+32, +64, +96
    const float4* wr = W + (size_t)n * K_VEC;
    float4 wreg[4];
#pragma unroll
    for (int k = 0; k < 4; k++) wreg[k] = __ldg(&wr[lane + 32 * k]);

    const float th = __ldg(&theta[n]);

    __shared__ int s_cnt[4];
    int cnt = 0;

    // 32 batch rows per warp, 2 at a time for MLP (8 LDG.128 in flight)
#pragma unroll 1
    for (int i = 0; i < 32; i += 2) {
        const int b0 = bb + i;
        const int b1 = bb + i + 1;
        const float4* x0 = x + ((size_t)b0 * N_DIM + n) * K_VEC;
        const float4* x1 = x + ((size_t)b1 * N_DIM + n) * K_VEC;

        float4 a0[4], a1[4];
#pragma unroll
        for (int k = 0; k < 4; k++) a0[k] = __ldcs(&x0[lane + 32 * k]);
#pragma unroll
        for (int k = 0; k < 4; k++) a1[k] = __ldcs(&x1[lane + 32 * k]);

        float acc0 = 0.0f, acc1 = 0.0f;
#pragma unroll
        for (int k = 0; k < 4; k++) {
            acc0 = fmaf(a0[k].x, wreg[k].x, acc0);
            acc0 = fmaf(a0[k].y, wreg[k].y, acc0);
            acc0 = fmaf(a0[k].z, wreg[k].z, acc0);
            acc0 = fmaf(a0[k].w, wreg[k].w, acc0);
            acc1 = fmaf(a1[k].x, wreg[k].x, acc1);
            acc1 = fmaf(a1[k].y, wreg[k].y, acc1);
            acc1 = fmaf(a1[k].z, wreg[k].z, acc1);
            acc1 = fmaf(a1[k].w, wreg[k].w, acc1);
        }

        // Butterfly reductions (interleaved to hide SHFL latency)
#pragma unroll
        for (int off = 16; off > 0; off >>= 1) {
            acc0 += __shfl_xor_sync(0xFFFFFFFFu, acc0, off);
            acc1 += __shfl_xor_sync(0xFFFFFFFFu, acc1, off);
        }

        if (lane == 0) {
            const float s0 = (acc0 >= th) ? 1.0f : 0.0f;
            const float s1 = (acc1 >= th) ? 1.0f : 0.0f;
            spikes[(size_t)b0 * N_DIM + n] = s0;
            spikes[(size_t)b1 * N_DIM + n] = s1;
            cnt += (int)s0 + (int)s1;
        }
    }

    if (lane == 0) s_cnt[w] = cnt;
    __syncthreads();

    // Thread 0 finalizes neuron n
    if (tid == 0) {
        const int total = s_cnt[0] + s_cnt[1] + s_cnt[2] + s_cnt[3];
        const float rate = (float)total * (1.0f / (float)B_DIM);
        const float rh = (1.0f - ALPHA) * r_hat[n] + ALPHA * rate;
        const float thn = theta[n] + THETA_LR * (rh - R_TARGET);
        rates[n]  = rate;
        r_hats[n] = rh;
        thetas[n] = thn;
    }
}

extern "C" void kernel_launch(void* const* d_in, const int* in_sizes, int n_in,
                              void* d_out, int out_size) {
    const float4* x     = (const float4*)d_in[0];   // [B, N, D, S] f32
    const float4* W     = (const float4*)d_in[1];   // [N, D, S] f32
    const float* theta  = (const float*)d_in[2];    // [N]
    const float* r_hat  = (const float*)d_in[3];    // [N]

    float* out    = (float*)d_out;
    float* spikes = out;                       // [B*N]
    float* rates  = out + B_DIM * N_DIM;       // [N]
    float* thetas = rates + N_DIM;             // [N]
    float* r_hats = thetas + N_DIM;            // [N]

    mpjrd_fused<<<N_DIM, 128>>>(x, W, theta, r_hat,
                                spikes, rates, thetas, r_hats);
}

// round 9
// speedup vs baseline: 1.0724x; 1.0007x over previous
#include <cuda_runtime.h>

// Shapes fixed by reference setup_inputs
#define B_DIM 128
#define N_DIM 1024
#define K_DIM 512            // D*S
#define K_VEC (K_DIM / 4)    // 128 float4 per row
#define ALPHA 0.05f
#define THETA_LR 0.1f
#define R_TARGET 0.1f

// Fully fused, software-pipelined kernel. One neuron per CTA.
// Grid: 1024 CTAs, block 128 (4 warps). Warp w owns batch rows [w*32, w*32+32).
// Double-buffered row pipeline: while row i computes (FMA + 5-SHFL butterfly +
// store, ~300 cyc with zero loads outstanding in the old version), row i+1's
// 4x LDG.128 are already in flight -> load duty cycle ~1.0 instead of ~0.75.
// Register budget kept <= ~72 (2 row buffers + W row + misc) so 7 CTAs/SM fit
// and all 1024 CTAs run in ONE wave (6.92 avg/SM) — a 3-buffer pipeline at
// ~80 regs would cap at 6 CTAs/SM and spill a 136-CTA second wave.
// Per-row summation order identical to the passing R4 kernel (bit-identical
// spikes). Full batch per CTA -> rate/theta/r_hat finalize in-kernel.

__device__ __forceinline__ float dot_row(const float4* __restrict__ a,
                                         const float4* __restrict__ wreg) {
    float acc = 0.0f;
#pragma unroll
    for (int k = 0; k < 4; k++) {
        acc = fmaf(a[k].x, wreg[k].x, acc);
        acc = fmaf(a[k].y, wreg[k].y, acc);
        acc = fmaf(a[k].z, wreg[k].z, acc);
        acc = fmaf(a[k].w, wreg[k].w, acc);
    }
#pragma unroll
    for (int off = 16; off > 0; off >>= 1)
        acc += __shfl_xor_sync(0xFFFFFFFFu, acc, off);
    return acc;
}

__global__ __launch_bounds__(128, 7) void mpjrd_fused(
    const float4* __restrict__ x,     // [B, N, 128] float4
    const float4* __restrict__ W,     // [N, 128] float4
    const float* __restrict__ theta,  // [N]
    const float* __restrict__ r_hat,  // [N]
    float* __restrict__ spikes,       // [B, N]
    float* __restrict__ rates,        // [N]
    float* __restrict__ thetas,       // [N]
    float* __restrict__ r_hats)       // [N]
{
    const int tid  = threadIdx.x;
    const int w    = tid >> 5;        // warp 0..3
    const int lane = tid & 31;
    const int n    = blockIdx.x;      // this CTA's neuron
    const int bb   = w * 32;          // first batch row for this warp

    // W row into registers: lane covers float4 indices lane, lane+32, +64, +96
    const float4* wr = W + (size_t)n * K_VEC;
    float4 wreg[4];
#pragma unroll
    for (int k = 0; k < 4; k++) wreg[k] = __ldg(&wr[lane + 32 * k]);

    const float th = __ldg(&theta[n]);

    // Base pointer for this warp's row stream: rows advance by N_DIM*K_VEC
    const float4* xr = x + ((size_t)bb * N_DIM + n) * K_VEC + lane;
    const size_t ROW = (size_t)N_DIM * K_VEC;

    __shared__ int s_cnt[4];
    int cnt = 0;

    float4 A[4], Bf[4];

    // Prologue: load row 0 into A
#pragma unroll
    for (int k = 0; k < 4; k++) A[k] = __ldcs(xr + 32 * k);

#pragma unroll 1
    for (int i = 0; i < 30; i += 2) {
        const float4* xi1 = xr + (size_t)(i + 1) * ROW;
        const float4* xi2 = xr + (size_t)(i + 2) * ROW;

        // load row i+1 into B, then compute row i from A
#pragma unroll
        for (int k = 0; k < 4; k++) Bf[k] = __ldcs(xi1 + 32 * k);
        {
            const float v = dot_row(A, wreg);
            if (lane == 0) {
                const float s = (v >= th) ? 1.0f : 0.0f;
                spikes[(size_t)(bb + i) * N_DIM + n] = s;
                cnt += (int)s;
            }
        }

        // load row i+2 into A, then compute row i+1 from B
#pragma unroll
        for (int k = 0; k < 4; k++) A[k] = __ldcs(xi2 + 32 * k);
        {
            const float v = dot_row(Bf, wreg);
            if (lane == 0) {
                const float s = (v >= th) ? 1.0f : 0.0f;
                spikes[(size_t)(bb + i + 1) * N_DIM + n] = s;
                cnt += (int)s;
            }
        }
    }

    // Epilogue: rows 30 (in A) and 31
    {
        const float4* xi31 = xr + (size_t)31 * ROW;
#pragma unroll
        for (int k = 0; k < 4; k++) Bf[k] = __ldcs(xi31 + 32 * k);

        const float v30 = dot_row(A, wreg);
        const float v31 = dot_row(Bf, wreg);
        if (lane == 0) {
            const float s30 = (v30 >= th) ? 1.0f : 0.0f;
            const float s31 = (v31 >= th) ? 1.0f : 0.0f;
            spikes[(size_t)(bb + 30) * N_DIM + n] = s30;
            spikes[(size_t)(bb + 31) * N_DIM + n] = s31;
            cnt += (int)s30 + (int)s31;
        }
    }

    if (lane == 0) s_cnt[w] = cnt;
    __syncthreads();

    if (tid == 0) {
        const int total = s_cnt[0] + s_cnt[1] + s_cnt[2] + s_cnt[3];
        const float rate = (float)total * (1.0f / (float)B_DIM);
        const float rh = (1.0f - ALPHA) * r_hat[n] + ALPHA * rate;
        const float thn = theta[n] + THETA_LR * (rh - R_TARGET);
        rates[n]  = rate;
        r_hats[n] = rh;
        thetas[n] = thn;
    }
}

extern "C" void kernel_launch(void* const* d_in, const int* in_sizes, int n_in,
                              void* d_out, int out_size) {
    const float4* x     = (const float4*)d_in[0];   // [B, N, D, S] f32
    const float4* W     = (const float4*)d_in[1];   // [N, D, S] f32
    const float* theta  = (const float*)d_in[2];    // [N]
    const float* r_hat  = (const float*)d_in[3];    // [N]

    float* out    = (float*)d_out;
    float* spikes = out;                       // [B*N]
    float* rates  = out + B_DIM * N_DIM;       // [N]
    float* thetas = rates + N_DIM;             // [N]
    float* r_hats = thetas + N_DIM;            // [N]

    mpjrd_fused<<<N_DIM, 128>>>(x, W, theta, r_hat,
                                spikes, rates, thetas, r_hats);
}